// round 1
// baseline (speedup 1.0000x reference)
#include <cuda_runtime.h>
#include <cstdint>

#define S_LEN 2048
#define DM    2048
#define NH    16
#define DK    128
#define NB    4

// -------- scratch (static __device__ arrays; no allocation allowed) --------
__device__ float g_Q[(size_t)NB * NH * S_LEN * DK];    // [b,h,s,dk]
__device__ float g_K[(size_t)NB * NH * S_LEN * DK];
__device__ float g_V[(size_t)NB * NH * S_LEN * DK];
__device__ float g_Attn[(size_t)NB * S_LEN * DM];      // [b,s, h*DK+v]

// -------- helpers --------
__device__ __forceinline__ uint32_t f2tf(float f) {
    uint32_t u;
    asm("cvt.rna.tf32.f32 %0, %1;" : "=r"(u) : "f"(f));
    return u;
}

__device__ __forceinline__ void mma_tf32(float c[4], const uint32_t a[4], const uint32_t b[2]) {
    asm volatile(
        "mma.sync.aligned.m16n8k8.row.col.f32.tf32.tf32.f32 "
        "{%0,%1,%2,%3}, {%4,%5,%6,%7}, {%8,%9}, {%0,%1,%2,%3};"
        : "+f"(c[0]), "+f"(c[1]), "+f"(c[2]), "+f"(c[3])
        : "r"(a[0]), "r"(a[1]), "r"(a[2]), "r"(a[3]), "r"(b[0]), "r"(b[1]));
}

// ============================================================================
// NT GEMM: C[M=8192, N=2048] = A[8192, 2048] * B[2048, 2048]^T  (tf32 MMA)
// MODE 0: plain row-major output C[r*2048 + c]
// MODE 1: scatter to [b, h, s, dk]  (r = b*2048+s, c = h*128+dk)
// Block tile 128x128, K-chunk 64, 256 threads (8 warps, 4x2), warp tile 32x64.
// ============================================================================
#define GPAD 68   // 64 + 4 padding (uint32 words)

template <int MODE>
__global__ __launch_bounds__(256, 1) void gemm_nt(const float* __restrict__ A,
                                                  const float* __restrict__ Bw,
                                                  float* __restrict__ C) {
    extern __shared__ uint32_t sm[];
    uint32_t* As = sm;                 // [128][GPAD]
    uint32_t* Bs = sm + 128 * GPAD;    // [128][GPAD]

    const int m0 = blockIdx.y * 128;
    const int n0 = blockIdx.x * 128;
    const int tid = threadIdx.x;
    const int warp = tid >> 5, lane = tid & 31;
    const int wm = warp >> 1, wn = warp & 1;
    const int la3 = lane & 3, lg = lane >> 2;

    float acc[2][8][4];
#pragma unroll
    for (int i = 0; i < 2; i++)
#pragma unroll
        for (int j = 0; j < 8; j++)
#pragma unroll
            for (int e = 0; e < 4; e++) acc[i][j][e] = 0.f;

    for (int k0 = 0; k0 < 2048; k0 += 64) {
#pragma unroll
        for (int p = 0; p < 8; p++) {
            int r  = (tid >> 4) + p * 16;
            int c4 = (tid & 15) * 4;
            float4 va = *(const float4*)&A[(size_t)(m0 + r) * 2048 + k0 + c4];
            uint32_t* da = &As[r * GPAD + c4];
            da[0] = f2tf(va.x); da[1] = f2tf(va.y); da[2] = f2tf(va.z); da[3] = f2tf(va.w);
            float4 vb = *(const float4*)&Bw[(size_t)(n0 + r) * 2048 + k0 + c4];
            uint32_t* db = &Bs[r * GPAD + c4];
            db[0] = f2tf(vb.x); db[1] = f2tf(vb.y); db[2] = f2tf(vb.z); db[3] = f2tf(vb.w);
        }
        __syncthreads();

#pragma unroll
        for (int kk = 0; kk < 8; kk++) {
            uint32_t af[2][4], bf[8][2];
            const int c = kk * 8 + la3;
#pragma unroll
            for (int mf = 0; mf < 2; mf++) {
                int r = wm * 32 + mf * 16 + lg;
                af[mf][0] = As[r * GPAD + c];
                af[mf][1] = As[(r + 8) * GPAD + c];
                af[mf][2] = As[r * GPAD + c + 4];
                af[mf][3] = As[(r + 8) * GPAD + c + 4];
            }
#pragma unroll
            for (int nf = 0; nf < 8; nf++) {
                int r = wn * 64 + nf * 8 + lg;
                bf[nf][0] = Bs[r * GPAD + c];
                bf[nf][1] = Bs[r * GPAD + c + 4];
            }
#pragma unroll
            for (int mf = 0; mf < 2; mf++)
#pragma unroll
                for (int nf = 0; nf < 8; nf++) mma_tf32(acc[mf][nf], af[mf], bf[nf]);
        }
        __syncthreads();
    }

#pragma unroll
    for (int mf = 0; mf < 2; mf++)
#pragma unroll
        for (int nf = 0; nf < 8; nf++)
#pragma unroll
            for (int e = 0; e < 4; e++) {
                int r = m0 + wm * 32 + mf * 16 + lg + ((e >= 2) ? 8 : 0);
                int c = n0 + wn * 64 + nf * 8 + la3 * 2 + (e & 1);
                float v = acc[mf][nf][e];
                if (MODE == 0) {
                    C[(size_t)r * 2048 + c] = v;
                } else {
                    int b = r >> 11, s = r & 2047;
                    int h = c >> 7, d = c & 127;
                    C[((((size_t)b * NH) + h) * S_LEN + s) * DK + d] = v;
                }
            }
}

// ============================================================================
// Flash attention (causal).  One block = 128 query rows of one (b,h).
// 256 threads (8 warps); each warp owns 16 query rows.
// BK = 64 key tile.  tf32 MMA for QK^T and PV; fp32 softmax.
// ============================================================================
#define QPAD 132  // 128 + 4
#define PPAD 68   // 64 + 4

__global__ __launch_bounds__(256, 1) void flash_attn() {
    extern __shared__ uint32_t sm[];
    uint32_t* Qs = sm;                      // [128][QPAD]
    uint32_t* Ks = Qs + 128 * QPAD;         // [64][QPAD]
    uint32_t* Vs = Ks + 64 * QPAD;          // [64][QPAD]
    uint32_t* Ps = Vs + 64 * QPAD;          // [128][PPAD]

    const int bh = blockIdx.y;
    const int q0 = blockIdx.x * 128;
    const float* Qg = g_Q + (size_t)bh * S_LEN * DK;
    const float* Kg = g_K + (size_t)bh * S_LEN * DK;
    const float* Vg = g_V + (size_t)bh * S_LEN * DK;

    const int tid = threadIdx.x;
    const int warp = tid >> 5, lane = tid & 31;
    const int la3 = lane & 3, lg = lane >> 2;

    // load Q tile (128 x 128 floats) -> tf32 smem
#pragma unroll
    for (int p = 0; p < 16; p++) {
        int i  = p * 256 + tid;      // float4 index
        int r  = i >> 5;
        int c4 = (i & 31) * 4;
        float4 v = *(const float4*)&Qg[(size_t)(q0 + r) * DK + c4];
        uint32_t* d = &Qs[r * QPAD + c4];
        d[0] = f2tf(v.x); d[1] = f2tf(v.y); d[2] = f2tf(v.z); d[3] = f2tf(v.w);
    }

    float m_prev0 = -1e30f, m_prev1 = -1e30f;
    float l0 = 0.f, l1 = 0.f;
    float o[16][4];
#pragma unroll
    for (int nf = 0; nf < 16; nf++)
#pragma unroll
        for (int e = 0; e < 4; e++) o[nf][e] = 0.f;

    const int qrow0 = q0 + warp * 16 + lg;       // this thread's first row
    const int warp_qmax = q0 + warp * 16 + 15;
    const int nkt = blockIdx.x * 2 + 2;          // key tiles needed (causal)
    const float sc = 0.08838834764831845f;       // 1/sqrt(128)

    for (int kt = 0; kt < nkt; kt++) {
        const int k0 = kt * 64;
        // load K,V tiles (64 x 128 each)
#pragma unroll
        for (int p = 0; p < 8; p++) {
            int i  = p * 256 + tid;
            int r  = i >> 5;
            int c4 = (i & 31) * 4;
            float4 vk = *(const float4*)&Kg[(size_t)(k0 + r) * DK + c4];
            uint32_t* dk = &Ks[r * QPAD + c4];
            dk[0] = f2tf(vk.x); dk[1] = f2tf(vk.y); dk[2] = f2tf(vk.z); dk[3] = f2tf(vk.w);
            float4 vv = *(const float4*)&Vg[(size_t)(k0 + r) * DK + c4];
            uint32_t* dv = &Vs[r * QPAD + c4];
            dv[0] = f2tf(vv.x); dv[1] = f2tf(vv.y); dv[2] = f2tf(vv.z); dv[3] = f2tf(vv.w);
        }
        __syncthreads();

        if (k0 <= warp_qmax) {  // tile not fully masked for this warp
            // ---- S = Q K^T (16 q x 64 k per warp) ----
            float s[8][4];
#pragma unroll
            for (int nf = 0; nf < 8; nf++)
#pragma unroll
                for (int e = 0; e < 4; e++) s[nf][e] = 0.f;

#pragma unroll
            for (int kk = 0; kk < 16; kk++) {
                const int c = kk * 8 + la3;
                uint32_t af[4];
                int r = warp * 16 + lg;
                af[0] = Qs[r * QPAD + c];
                af[1] = Qs[(r + 8) * QPAD + c];
                af[2] = Qs[r * QPAD + c + 4];
                af[3] = Qs[(r + 8) * QPAD + c + 4];
                uint32_t bf[8][2];
#pragma unroll
                for (int nf = 0; nf < 8; nf++) {
                    int br = nf * 8 + lg;
                    bf[nf][0] = Ks[br * QPAD + c];
                    bf[nf][1] = Ks[br * QPAD + c + 4];
                }
#pragma unroll
                for (int nf = 0; nf < 8; nf++) mma_tf32(s[nf], af, bf[nf]);
            }

            // ---- scale + causal mask + row max ----
            float mx0 = -1e30f, mx1 = -1e30f;
#pragma unroll
            for (int nf = 0; nf < 8; nf++)
#pragma unroll
                for (int e = 0; e < 4; e++) {
                    int col = k0 + nf * 8 + la3 * 2 + (e & 1);
                    int qr  = qrow0 + ((e >= 2) ? 8 : 0);
                    float v = s[nf][e] * sc;
                    if (col > qr) v = -1e30f;
                    s[nf][e] = v;
                    if (e < 2) { mx0 = fmaxf(mx0, v); } else { mx1 = fmaxf(mx1, v); }
                }
            mx0 = fmaxf(mx0, __shfl_xor_sync(0xffffffff, mx0, 1));
            mx0 = fmaxf(mx0, __shfl_xor_sync(0xffffffff, mx0, 2));
            mx1 = fmaxf(mx1, __shfl_xor_sync(0xffffffff, mx1, 1));
            mx1 = fmaxf(mx1, __shfl_xor_sync(0xffffffff, mx1, 2));

            float mn0 = fmaxf(m_prev0, mx0);
            float mn1 = fmaxf(m_prev1, mx1);

            float sum0 = 0.f, sum1 = 0.f;
#pragma unroll
            for (int nf = 0; nf < 8; nf++)
#pragma unroll
                for (int e = 0; e < 4; e++) {
                    float p = __expf(s[nf][e] - ((e < 2) ? mn0 : mn1));
                    s[nf][e] = p;
                    if (e < 2) sum0 += p; else sum1 += p;
                }
            sum0 += __shfl_xor_sync(0xffffffff, sum0, 1);
            sum0 += __shfl_xor_sync(0xffffffff, sum0, 2);
            sum1 += __shfl_xor_sync(0xffffffff, sum1, 1);
            sum1 += __shfl_xor_sync(0xffffffff, sum1, 2);

            float corr0 = __expf(m_prev0 - mn0);
            float corr1 = __expf(m_prev1 - mn1);
            l0 = l0 * corr0 + sum0;
            l1 = l1 * corr1 + sum1;
            m_prev0 = mn0; m_prev1 = mn1;

#pragma unroll
            for (int nf = 0; nf < 16; nf++) {
                o[nf][0] *= corr0; o[nf][1] *= corr0;
                o[nf][2] *= corr1; o[nf][3] *= corr1;
            }

            // ---- stash P (tf32) into warp-private smem ----
#pragma unroll
            for (int nf = 0; nf < 8; nf++)
#pragma unroll
                for (int e = 0; e < 4; e++) {
                    int r = warp * 16 + lg + ((e >= 2) ? 8 : 0);
                    int c = nf * 8 + la3 * 2 + (e & 1);
                    Ps[r * PPAD + c] = f2tf(s[nf][e]);
                }
            __syncwarp();

            // ---- O += P V (16 q x 128 v per warp) ----
#pragma unroll
            for (int kk = 0; kk < 8; kk++) {
                uint32_t af[4];
                int r = warp * 16 + lg;
                int c = kk * 8 + la3;
                af[0] = Ps[r * PPAD + c];
                af[1] = Ps[(r + 8) * PPAD + c];
                af[2] = Ps[r * PPAD + c + 4];
                af[3] = Ps[(r + 8) * PPAD + c + 4];
#pragma unroll
                for (int nf = 0; nf < 16; nf++) {
                    uint32_t bf[2];
                    bf[0] = Vs[(kk * 8 + la3) * QPAD + nf * 8 + lg];
                    bf[1] = Vs[(kk * 8 + la3 + 4) * QPAD + nf * 8 + lg];
                    mma_tf32(o[nf], af, bf);
                }
            }
        }
        __syncthreads();
    }

    // ---- epilogue: normalize, write [b, s, h*DK + v] ----
    const int b = bh >> 4, h = bh & 15;
    float inv0 = 1.f / l0, inv1 = 1.f / l1;
#pragma unroll
    for (int nf = 0; nf < 16; nf++)
#pragma unroll
        for (int e = 0; e < 4; e++) {
            int q = qrow0 + ((e >= 2) ? 8 : 0);
            int v = nf * 8 + la3 * 2 + (e & 1);
            float val = o[nf][e] * ((e < 2) ? inv0 : inv1);
            g_Attn[((size_t)b * S_LEN + q) * DM + h * DK + v] = val;
        }
}

// ============================================================================
// launch
// ============================================================================
extern "C" void kernel_launch(void* const* d_in, const int* in_sizes, int n_in,
                              void* d_out, int out_size) {
    const float* x  = (const float*)d_in[0];
    const float* WQ = (const float*)d_in[1];
    const float* WK = (const float*)d_in[2];
    const float* WV = (const float*)d_in[3];
    const float* WO = (const float*)d_in[4];
    float* out = (float*)d_out;

    float *pQ, *pK, *pV, *pA;
    cudaGetSymbolAddress((void**)&pQ, g_Q);
    cudaGetSymbolAddress((void**)&pK, g_K);
    cudaGetSymbolAddress((void**)&pV, g_V);
    cudaGetSymbolAddress((void**)&pA, g_Attn);

    const int gemm_smem  = 2 * 128 * GPAD * 4;                       // 69632
    const int flash_smem = (128 * QPAD + 2 * 64 * QPAD + 128 * PPAD) * 4;  // 169984
    cudaFuncSetAttribute(gemm_nt<0>, cudaFuncAttributeMaxDynamicSharedMemorySize, gemm_smem);
    cudaFuncSetAttribute(gemm_nt<1>, cudaFuncAttributeMaxDynamicSharedMemorySize, gemm_smem);
    cudaFuncSetAttribute(flash_attn, cudaFuncAttributeMaxDynamicSharedMemorySize, flash_smem);

    dim3 ggrid(16, 64);   // N/128, M/128
    dim3 blk(256);

    gemm_nt<1><<<ggrid, blk, gemm_smem>>>(x, WQ, pQ);
    gemm_nt<1><<<ggrid, blk, gemm_smem>>>(x, WK, pK);
    gemm_nt<1><<<ggrid, blk, gemm_smem>>>(x, WV, pV);

    dim3 fgrid(16, 64);   // S/128 q-tiles, B*H
    flash_attn<<<fgrid, blk, flash_smem>>>();

    gemm_nt<0><<<ggrid, blk, gemm_smem>>>(pA, WO, out);
}

// round 2
// speedup vs baseline: 1.1669x; 1.1669x over previous
#include <cuda_runtime.h>
#include <cstdint>

#define S_LEN 2048
#define DM    2048
#define NH    16
#define DK    128
#define NB    4

// -------- scratch (static __device__ arrays; no allocation allowed) --------
__device__ float g_Q[(size_t)NB * NH * S_LEN * DK];    // [b,h,s,dk] tf32-rounded
__device__ float g_K[(size_t)NB * NH * S_LEN * DK];
__device__ float g_V[(size_t)NB * NH * S_LEN * DK];
__device__ float g_Attn[(size_t)NB * S_LEN * DM];      // [b,s,h*DK+v] tf32-rounded
__device__ float g_xt[(size_t)NB * S_LEN * DM];        // x, tf32-rounded
__device__ float g_Wt[4][(size_t)DM * DM];             // W_Q,W_K,W_V,W_O tf32-rounded

// -------- helpers --------
__device__ __forceinline__ uint32_t f2tf(float f) {
    uint32_t u;
    asm("cvt.rna.tf32.f32 %0, %1;" : "=r"(u) : "f"(f));
    return u;
}

__device__ __forceinline__ void mma_tf32(float c[4], const uint32_t a[4], const uint32_t b[2]) {
    asm volatile(
        "mma.sync.aligned.m16n8k8.row.col.f32.tf32.tf32.f32 "
        "{%0,%1,%2,%3}, {%4,%5,%6,%7}, {%8,%9}, {%0,%1,%2,%3};"
        : "+f"(c[0]), "+f"(c[1]), "+f"(c[2]), "+f"(c[3])
        : "r"(a[0]), "r"(a[1]), "r"(a[2]), "r"(a[3]), "r"(b[0]), "r"(b[1]));
}

__device__ __forceinline__ void cp16(void* sptr, const void* g) {
    uint32_t sa = (uint32_t)__cvta_generic_to_shared(sptr);
    asm volatile("cp.async.cg.shared.global [%0], [%1], 16;" :: "r"(sa), "l"(g));
}
__device__ __forceinline__ void cp_commit() { asm volatile("cp.async.commit_group;"); }
template <int N>
__device__ __forceinline__ void cp_wait() { asm volatile("cp.async.wait_group %0;" :: "n"(N)); }

// ============================================================================
// tf32 pre-round pass (elementwise, vectorized)
// ============================================================================
__global__ void cvt_tf32(const float* __restrict__ in, float* __restrict__ out, int n4) {
    int i = blockIdx.x * blockDim.x + threadIdx.x;
    int st = gridDim.x * blockDim.x;
    for (; i < n4; i += st) {
        float4 v = ((const float4*)in)[i];
        uint4 u;
        u.x = f2tf(v.x); u.y = f2tf(v.y); u.z = f2tf(v.z); u.w = f2tf(v.w);
        ((uint4*)out)[i] = u;
    }
}

// ============================================================================
// NT GEMM: C[M=8192, N=2048] = A[8192,2048] * B[2048,2048]^T  (tf32 MMA)
// Inputs are pre-rounded tf32 bits — no cvt anywhere in the kernel.
// Block tile 256x128, 512 threads (16 warps, 8x2), warp tile 32x64.
// BK=32, 4-stage cp.async pipeline.
// MODE 0: row-major output.  MODE 1: scatter to [b,h,s,dk], tf32-rounded.
// ============================================================================
#define BK   32
#define LDP  36            // 32 + 4 pad (words)
#define STG  4
#define A_STAGE (256 * LDP)
#define B_STAGE (128 * LDP)

template <int MODE>
__global__ __launch_bounds__(512, 1) void gemm_nt(const float* __restrict__ A,
                                                  const float* __restrict__ Bw,
                                                  float* __restrict__ C) {
    extern __shared__ uint32_t sm[];
    uint32_t* As = sm;                    // [STG][256][LDP]
    uint32_t* Bs = sm + STG * A_STAGE;    // [STG][128][LDP]

    const int m0 = blockIdx.y * 256;
    const int n0 = blockIdx.x * 128;
    const int tid = threadIdx.x;
    const int warp = tid >> 5, lane = tid & 31;
    const int wm = warp >> 1, wn = warp & 1;      // 8 x 2 warps
    const int la3 = lane & 3, lg = lane >> 2;

    const int lr = tid >> 3;          // 0..63
    const int lc = (tid & 7) * 4;     // float col

    float acc[2][8][4];
#pragma unroll
    for (int i = 0; i < 2; i++)
#pragma unroll
        for (int j = 0; j < 8; j++)
#pragma unroll
            for (int e = 0; e < 4; e++) acc[i][j][e] = 0.f;

    auto loadStage = [&](int s, int k0) {
        uint32_t* as = As + s * A_STAGE;
        uint32_t* bs = Bs + s * B_STAGE;
#pragma unroll
        for (int p = 0; p < 4; p++) {
            int row = lr + p * 64;
            cp16(as + row * LDP + lc, &A[(size_t)(m0 + row) * 2048 + k0 + lc]);
        }
#pragma unroll
        for (int p = 0; p < 2; p++) {
            int row = lr + p * 64;
            cp16(bs + row * LDP + lc, &Bw[(size_t)(n0 + row) * 2048 + k0 + lc]);
        }
    };

    // prologue: fill STG-1 stages
#pragma unroll
    for (int s = 0; s < STG - 1; s++) { loadStage(s, s * BK); cp_commit(); }

    const int NCH = 2048 / BK;   // 64
    for (int ch = 0; ch < NCH; ch++) {
        cp_wait<STG - 2>();
        __syncthreads();
        int pre = ch + STG - 1;
        if (pre < NCH) loadStage(pre & (STG - 1), pre * BK);
        cp_commit();

        uint32_t* as = As + (ch & (STG - 1)) * A_STAGE;
        uint32_t* bs = Bs + (ch & (STG - 1)) * B_STAGE;
#pragma unroll
        for (int kk = 0; kk < 4; kk++) {
            const int c = kk * 8 + la3;
            uint32_t af[2][4], bf[8][2];
#pragma unroll
            for (int mf = 0; mf < 2; mf++) {
                int r = wm * 32 + mf * 16 + lg;
                af[mf][0] = as[r * LDP + c];
                af[mf][1] = as[(r + 8) * LDP + c];
                af[mf][2] = as[r * LDP + c + 4];
                af[mf][3] = as[(r + 8) * LDP + c + 4];
            }
#pragma unroll
            for (int nf = 0; nf < 8; nf++) {
                int r = wn * 64 + nf * 8 + lg;
                bf[nf][0] = bs[r * LDP + c];
                bf[nf][1] = bs[r * LDP + c + 4];
            }
#pragma unroll
            for (int mf = 0; mf < 2; mf++)
#pragma unroll
                for (int nf = 0; nf < 8; nf++) mma_tf32(acc[mf][nf], af[mf], bf[nf]);
        }
    }

#pragma unroll
    for (int mf = 0; mf < 2; mf++)
#pragma unroll
        for (int nf = 0; nf < 8; nf++)
#pragma unroll
            for (int e = 0; e < 4; e++) {
                int r = m0 + wm * 32 + mf * 16 + lg + ((e >= 2) ? 8 : 0);
                int c = n0 + wn * 64 + nf * 8 + la3 * 2 + (e & 1);
                float v = acc[mf][nf][e];
                if (MODE == 0) {
                    C[(size_t)r * 2048 + c] = v;
                } else {
                    int b = r >> 11, s = r & 2047;
                    int h = c >> 7, d = c & 127;
                    C[((((size_t)b * NH) + h) * S_LEN + s) * DK + d] = __uint_as_float(f2tf(v));
                }
            }
}

// ============================================================================
// Flash attention (causal).  One block = 128 query rows of one (b,h).
// 256 threads (8 warps); each warp owns 16 query rows.
// Q held in registers; K/V double-buffered via cp.async (BK=64).
// All operands pre-rounded tf32 — no cvt on the load path.
// ============================================================================
#define KLD    132              // 128 + 4 pad
#define PPAD   68
#define KSTAGE (64 * KLD)

__global__ __launch_bounds__(256, 1) void flash_attn() {
    extern __shared__ uint32_t sm[];
    uint32_t* Ks = sm;                    // [2][64][KLD]
    uint32_t* Vs = sm + 2 * KSTAGE;       // [2][64][KLD]
    uint32_t* Ps = sm + 4 * KSTAGE;       // [128][PPAD]

    const int bh = blockIdx.y;
    const int q0 = blockIdx.x * 128;
    const float* Qg = g_Q + (size_t)bh * S_LEN * DK;
    const float* Kg = g_K + (size_t)bh * S_LEN * DK;
    const float* Vg = g_V + (size_t)bh * S_LEN * DK;

    const int tid = threadIdx.x;
    const int warp = tid >> 5, lane = tid & 31;
    const int la3 = lane & 3, lg = lane >> 2;

    // ---- Q tile into registers (one-time) ----
    uint32_t qf[16][4];
    {
        const float* Qr0 = Qg + (size_t)(q0 + warp * 16 + lg) * DK;
#pragma unroll
        for (int kk = 0; kk < 16; kk++) {
            int c = kk * 8 + la3;
            qf[kk][0] = __float_as_uint(Qr0[c]);
            qf[kk][1] = __float_as_uint(Qr0[8 * DK + c]);
            qf[kk][2] = __float_as_uint(Qr0[c + 4]);
            qf[kk][3] = __float_as_uint(Qr0[8 * DK + c + 4]);
        }
    }

    const int lrr = tid >> 5;          // 0..7
    const int lcc = (tid & 31) * 4;    // float col
    auto loadKV = [&](int s, int k0) {
        uint32_t* ks = Ks + s * KSTAGE;
        uint32_t* vs = Vs + s * KSTAGE;
#pragma unroll
        for (int p = 0; p < 8; p++) {
            int row = lrr + p * 8;
            cp16(ks + row * KLD + lcc, &Kg[(size_t)(k0 + row) * DK + lcc]);
            cp16(vs + row * KLD + lcc, &Vg[(size_t)(k0 + row) * DK + lcc]);
        }
    };

    float m_prev0 = -1e30f, m_prev1 = -1e30f;
    float l0 = 0.f, l1 = 0.f;
    float o[16][4];
#pragma unroll
    for (int nf = 0; nf < 16; nf++)
#pragma unroll
        for (int e = 0; e < 4; e++) o[nf][e] = 0.f;

    const int qrow0 = q0 + warp * 16 + lg;
    const int warp_qmax = q0 + warp * 16 + 15;
    const int nkt = blockIdx.x * 2 + 2;
    const float sc = 0.08838834764831845f;   // 1/sqrt(128)

    loadKV(0, 0);
    cp_commit();

    for (int kt = 0; kt < nkt; kt++) {
        const int k0 = kt * 64;
        if (kt + 1 < nkt) {
            loadKV((kt + 1) & 1, (kt + 1) * 64);
            cp_commit();
            cp_wait<1>();
        } else {
            cp_wait<0>();
        }
        __syncthreads();

        const int st = kt & 1;
        const uint32_t* ks = Ks + st * KSTAGE;
        const uint32_t* vs = Vs + st * KSTAGE;

        if (k0 <= warp_qmax) {
            // ---- S = Q K^T ----
            float s[8][4];
#pragma unroll
            for (int nf = 0; nf < 8; nf++)
#pragma unroll
                for (int e = 0; e < 4; e++) s[nf][e] = 0.f;

#pragma unroll
            for (int kk = 0; kk < 16; kk++) {
                const int c = kk * 8 + la3;
                uint32_t bf[8][2];
#pragma unroll
                for (int nf = 0; nf < 8; nf++) {
                    int br = nf * 8 + lg;
                    bf[nf][0] = ks[br * KLD + c];
                    bf[nf][1] = ks[br * KLD + c + 4];
                }
#pragma unroll
                for (int nf = 0; nf < 8; nf++) mma_tf32(s[nf], qf[kk], bf[nf]);
            }

            // ---- scale + causal mask + running softmax ----
            float mx0 = -1e30f, mx1 = -1e30f;
#pragma unroll
            for (int nf = 0; nf < 8; nf++)
#pragma unroll
                for (int e = 0; e < 4; e++) {
                    int col = k0 + nf * 8 + la3 * 2 + (e & 1);
                    int qr  = qrow0 + ((e >= 2) ? 8 : 0);
                    float v = s[nf][e] * sc;
                    if (col > qr) v = -1e30f;
                    s[nf][e] = v;
                    if (e < 2) { mx0 = fmaxf(mx0, v); } else { mx1 = fmaxf(mx1, v); }
                }
            mx0 = fmaxf(mx0, __shfl_xor_sync(0xffffffff, mx0, 1));
            mx0 = fmaxf(mx0, __shfl_xor_sync(0xffffffff, mx0, 2));
            mx1 = fmaxf(mx1, __shfl_xor_sync(0xffffffff, mx1, 1));
            mx1 = fmaxf(mx1, __shfl_xor_sync(0xffffffff, mx1, 2));

            float mn0 = fmaxf(m_prev0, mx0);
            float mn1 = fmaxf(m_prev1, mx1);

            float sum0 = 0.f, sum1 = 0.f;
#pragma unroll
            for (int nf = 0; nf < 8; nf++)
#pragma unroll
                for (int e = 0; e < 4; e++) {
                    float p = __expf(s[nf][e] - ((e < 2) ? mn0 : mn1));
                    s[nf][e] = p;
                    if (e < 2) sum0 += p; else sum1 += p;
                }
            sum0 += __shfl_xor_sync(0xffffffff, sum0, 1);
            sum0 += __shfl_xor_sync(0xffffffff, sum0, 2);
            sum1 += __shfl_xor_sync(0xffffffff, sum1, 1);
            sum1 += __shfl_xor_sync(0xffffffff, sum1, 2);

            float corr0 = __expf(m_prev0 - mn0);
            float corr1 = __expf(m_prev1 - mn1);
            l0 = l0 * corr0 + sum0;
            l1 = l1 * corr1 + sum1;
            m_prev0 = mn0; m_prev1 = mn1;

#pragma unroll
            for (int nf = 0; nf < 16; nf++) {
                o[nf][0] *= corr0; o[nf][1] *= corr0;
                o[nf][2] *= corr1; o[nf][3] *= corr1;
            }

            // ---- stash P (tf32) in warp-private smem rows ----
#pragma unroll
            for (int nf = 0; nf < 8; nf++)
#pragma unroll
                for (int e = 0; e < 4; e++) {
                    int r = warp * 16 + lg + ((e >= 2) ? 8 : 0);
                    int c = nf * 8 + la3 * 2 + (e & 1);
                    Ps[r * PPAD + c] = f2tf(s[nf][e]);
                }
            __syncwarp();

            // ---- O += P V ----
#pragma unroll
            for (int kk = 0; kk < 8; kk++) {
                uint32_t af[4];
                int r = warp * 16 + lg;
                int c = kk * 8 + la3;
                af[0] = Ps[r * PPAD + c];
                af[1] = Ps[(r + 8) * PPAD + c];
                af[2] = Ps[r * PPAD + c + 4];
                af[3] = Ps[(r + 8) * PPAD + c + 4];
#pragma unroll
                for (int nf = 0; nf < 16; nf++) {
                    uint32_t bf[2];
                    bf[0] = vs[(kk * 8 + la3) * KLD + nf * 8 + lg];
                    bf[1] = vs[(kk * 8 + la3 + 4) * KLD + nf * 8 + lg];
                    mma_tf32(o[nf], af, bf);
                }
            }
        }
        __syncthreads();
    }

    // ---- epilogue: normalize, tf32-round, write [b, s, h*DK + v] ----
    const int b = bh >> 4, h = bh & 15;
    float inv0 = 1.f / l0, inv1 = 1.f / l1;
#pragma unroll
    for (int nf = 0; nf < 16; nf++)
#pragma unroll
        for (int e = 0; e < 4; e++) {
            int q = qrow0 + ((e >= 2) ? 8 : 0);
            int v = nf * 8 + la3 * 2 + (e & 1);
            float val = o[nf][e] * ((e < 2) ? inv0 : inv1);
            g_Attn[((size_t)b * S_LEN + q) * DM + h * DK + v] = __uint_as_float(f2tf(val));
        }
}

// ============================================================================
// launch
// ============================================================================
extern "C" void kernel_launch(void* const* d_in, const int* in_sizes, int n_in,
                              void* d_out, int out_size) {
    const float* x  = (const float*)d_in[0];
    const float* WQ = (const float*)d_in[1];
    const float* WK = (const float*)d_in[2];
    const float* WV = (const float*)d_in[3];
    const float* WO = (const float*)d_in[4];
    float* out = (float*)d_out;

    float *pQ, *pK, *pV, *pA, *pXt, *pWt;
    cudaGetSymbolAddress((void**)&pQ,  g_Q);
    cudaGetSymbolAddress((void**)&pK,  g_K);
    cudaGetSymbolAddress((void**)&pV,  g_V);
    cudaGetSymbolAddress((void**)&pA,  g_Attn);
    cudaGetSymbolAddress((void**)&pXt, g_xt);
    cudaGetSymbolAddress((void**)&pWt, g_Wt);

    const size_t WSZ = (size_t)DM * DM;
    const int gemm_smem  = STG * (A_STAGE + B_STAGE) * 4;                  // 221184
    const int flash_smem = (4 * KSTAGE + 128 * PPAD) * 4;                  // 169984
    cudaFuncSetAttribute(gemm_nt<0>, cudaFuncAttributeMaxDynamicSharedMemorySize, gemm_smem);
    cudaFuncSetAttribute(gemm_nt<1>, cudaFuncAttributeMaxDynamicSharedMemorySize, gemm_smem);
    cudaFuncSetAttribute(flash_attn, cudaFuncAttributeMaxDynamicSharedMemorySize, flash_smem);

    // tf32 pre-round
    cvt_tf32<<<1024, 256>>>(x,  pXt,           (NB * S_LEN * DM) / 4);
    cvt_tf32<<<512,  256>>>(WQ, pWt + 0 * WSZ, (int)(WSZ / 4));
    cvt_tf32<<<512,  256>>>(WK, pWt + 1 * WSZ, (int)(WSZ / 4));
    cvt_tf32<<<512,  256>>>(WV, pWt + 2 * WSZ, (int)(WSZ / 4));
    cvt_tf32<<<512,  256>>>(WO, pWt + 3 * WSZ, (int)(WSZ / 4));

    dim3 ggrid(16, 32);   // N/128, M/256
    dim3 gblk(512);
    gemm_nt<1><<<ggrid, gblk, gemm_smem>>>(pXt, pWt + 0 * WSZ, pQ);
    gemm_nt<1><<<ggrid, gblk, gemm_smem>>>(pXt, pWt + 1 * WSZ, pK);
    gemm_nt<1><<<ggrid, gblk, gemm_smem>>>(pXt, pWt + 2 * WSZ, pV);

    dim3 fgrid(16, 64);   // S/128 q-tiles, B*H
    flash_attn<<<fgrid, 256, flash_smem>>>();

    gemm_nt<0><<<ggrid, gblk, gemm_smem>>>(pA, pWt + 3 * WSZ, out);
}

// round 3
// speedup vs baseline: 2.3148x; 1.9836x over previous
#include <cuda_runtime.h>
#include <cuda_fp16.h>
#include <cstdint>

#define S_LEN 2048
#define DM    2048
#define NH    16
#define DK    128
#define NB    4

// -------- scratch (static __device__ arrays) --------
__device__ __half g_Q[(size_t)NB * NH * S_LEN * DK];    // [b,h,s,dk] fp16
__device__ __half g_K[(size_t)NB * NH * S_LEN * DK];
__device__ __half g_V[(size_t)NB * NH * S_LEN * DK];
__device__ __half g_Attn[(size_t)NB * S_LEN * DM];      // [b,s,h*DK+v] fp16
__device__ __half g_xh[(size_t)NB * S_LEN * DM];        // x fp16
__device__ __half g_Wh[4][(size_t)DM * DM];             // weights fp16

// -------- helpers --------
__device__ __forceinline__ void mma_f16(float c[4], const uint32_t a[4], const uint32_t b[2]) {
    asm volatile(
        "mma.sync.aligned.m16n8k16.row.col.f32.f16.f16.f32 "
        "{%0,%1,%2,%3}, {%4,%5,%6,%7}, {%8,%9}, {%0,%1,%2,%3};"
        : "+f"(c[0]), "+f"(c[1]), "+f"(c[2]), "+f"(c[3])
        : "r"(a[0]), "r"(a[1]), "r"(a[2]), "r"(a[3]), "r"(b[0]), "r"(b[1]));
}

__device__ __forceinline__ void ldsm4(uint32_t& r0, uint32_t& r1, uint32_t& r2, uint32_t& r3,
                                      const void* p) {
    uint32_t a = (uint32_t)__cvta_generic_to_shared(p);
    asm volatile("ldmatrix.sync.aligned.m8n8.x4.shared.b16 {%0,%1,%2,%3}, [%4];"
                 : "=r"(r0), "=r"(r1), "=r"(r2), "=r"(r3) : "r"(a));
}
__device__ __forceinline__ void ldsm4t(uint32_t& r0, uint32_t& r1, uint32_t& r2, uint32_t& r3,
                                       const void* p) {
    uint32_t a = (uint32_t)__cvta_generic_to_shared(p);
    asm volatile("ldmatrix.sync.aligned.m8n8.x4.trans.shared.b16 {%0,%1,%2,%3}, [%4];"
                 : "=r"(r0), "=r"(r1), "=r"(r2), "=r"(r3) : "r"(a));
}

__device__ __forceinline__ void cp16(void* sptr, const void* g) {
    uint32_t sa = (uint32_t)__cvta_generic_to_shared(sptr);
    asm volatile("cp.async.cg.shared.global [%0], [%1], 16;" :: "r"(sa), "l"(g));
}
__device__ __forceinline__ void cp_commit() { asm volatile("cp.async.commit_group;"); }
template <int N>
__device__ __forceinline__ void cp_wait() { asm volatile("cp.async.wait_group %0;" :: "n"(N)); }

// ============================================================================
// f32 -> f16 conversion (vectorized)
// ============================================================================
__global__ void cvt_f16(const float* __restrict__ in, __half* __restrict__ out, int n4) {
    int i = blockIdx.x * blockDim.x + threadIdx.x;
    int st = gridDim.x * blockDim.x;
    for (; i < n4; i += st) {
        float4 v = ((const float4*)in)[i];
        __half2 h0 = __floats2half2_rn(v.x, v.y);
        __half2 h1 = __floats2half2_rn(v.z, v.w);
        uint2 u;
        u.x = *(uint32_t*)&h0; u.y = *(uint32_t*)&h1;
        ((uint2*)out)[i] = u;
    }
}

// ============================================================================
// NT GEMM (fp16 in, fp32 acc): C[8192,2048] = A[8192,2048] * B[2048,2048]^T
// Block 256x128, 512 thr (16 warps 8x2), warp 32x64, BK=32, 4-stage cp.async.
// MODE 0: C float row-major.  MODE 1: C half scattered [b,h,s,dk].
// ============================================================================
#define BK     32
#define APITCH 40                 // halfs per row (32 + 8 pad -> 80B, conflict-free ldmatrix)
#define STG    4
#define A_ST   (256 * APITCH)     // halfs
#define B_ST   (128 * APITCH)

template <int MODE>
__global__ __launch_bounds__(512, 1) void gemm_nt(const __half* __restrict__ A,
                                                  const __half* __restrict__ Bw,
                                                  void* __restrict__ Cv) {
    extern __shared__ __half sm[];
    __half* As = sm;                 // [STG][256][APITCH]
    __half* Bs = sm + STG * A_ST;    // [STG][128][APITCH]

    const int m0 = blockIdx.y * 256;
    const int n0 = blockIdx.x * 128;
    const int tid = threadIdx.x;
    const int warp = tid >> 5, lane = tid & 31;
    const int wm = warp >> 1, wn = warp & 1;
    const int la3 = lane & 3, lg = lane >> 2;

    float acc[2][8][4];
#pragma unroll
    for (int i = 0; i < 2; i++)
#pragma unroll
        for (int j = 0; j < 8; j++)
#pragma unroll
            for (int e = 0; e < 4; e++) acc[i][j][e] = 0.f;

    auto loadStage = [&](int s, int k0) {
        __half* as = As + s * A_ST;
        __half* bs = Bs + s * B_ST;
        // A: 256 rows x 4 chunks (8 halfs) = 1024 ; 2 per thread
#pragma unroll
        for (int p = 0; p < 2; p++) {
            int i = tid + p * 512;
            int r = i >> 2, c8 = (i & 3) * 8;
            cp16(as + r * APITCH + c8, &A[(size_t)(m0 + r) * 2048 + k0 + c8]);
        }
        // B: 128 rows x 4 chunks = 512 ; 1 per thread
        {
            int r = tid >> 2, c8 = (tid & 3) * 8;
            cp16(bs + r * APITCH + c8, &Bw[(size_t)(n0 + r) * 2048 + k0 + c8]);
        }
    };

#pragma unroll
    for (int s = 0; s < STG - 1; s++) { loadStage(s, s * BK); cp_commit(); }

    // ldmatrix lane-address components
    const int a_row = lane & 15, a_col = (lane >> 4) * 8;                 // A frags
    const int b_row = (lane & 7) + ((lane >> 4) & 1) * 8;                 // B frags
    const int b_col = ((lane >> 3) & 1) * 8;

    const int NCH = 2048 / BK;
    for (int ch = 0; ch < NCH; ch++) {
        cp_wait<STG - 2>();
        __syncthreads();
        int pre = ch + STG - 1;
        if (pre < NCH) loadStage(pre & (STG - 1), pre * BK);
        cp_commit();

        const __half* as = As + (ch & (STG - 1)) * A_ST;
        const __half* bs = Bs + (ch & (STG - 1)) * B_ST;
#pragma unroll
        for (int kk = 0; kk < 2; kk++) {
            uint32_t af[2][4], bf[8][2];
#pragma unroll
            for (int mf = 0; mf < 2; mf++)
                ldsm4(af[mf][0], af[mf][1], af[mf][2], af[mf][3],
                      as + (wm * 32 + mf * 16 + a_row) * APITCH + kk * 16 + a_col);
#pragma unroll
            for (int j = 0; j < 4; j++) {
                uint32_t r0, r1, r2, r3;
                ldsm4(r0, r1, r2, r3,
                      bs + (wn * 64 + j * 16 + b_row) * APITCH + kk * 16 + b_col);
                bf[2 * j][0] = r0; bf[2 * j][1] = r1;
                bf[2 * j + 1][0] = r2; bf[2 * j + 1][1] = r3;
            }
#pragma unroll
            for (int mf = 0; mf < 2; mf++)
#pragma unroll
                for (int nf = 0; nf < 8; nf++) mma_f16(acc[mf][nf], af[mf], bf[nf]);
        }
    }

#pragma unroll
    for (int mf = 0; mf < 2; mf++)
#pragma unroll
        for (int nf = 0; nf < 8; nf++)
#pragma unroll
            for (int ep = 0; ep < 2; ep++) {
                int r = m0 + wm * 32 + mf * 16 + lg + ep * 8;
                int c = n0 + wn * 64 + nf * 8 + la3 * 2;
                float v0 = acc[mf][nf][2 * ep], v1 = acc[mf][nf][2 * ep + 1];
                if (MODE == 0) {
                    float2 f2 = make_float2(v0, v1);
                    *(float2*)&((float*)Cv)[(size_t)r * 2048 + c] = f2;
                } else {
                    int b = r >> 11, s = r & 2047;
                    int h = c >> 7, d = c & 127;
                    __half2 h2 = __floats2half2_rn(v0, v1);
                    *(__half2*)&((__half*)Cv)[((((size_t)b * NH) + h) * S_LEN + s) * DK + d] = h2;
                }
            }
}

// ============================================================================
// Flash attention (causal, fp16).  Block = 128 q-rows of one (b,h), 256 thr.
// Q in registers, K/V double-buffered cp.async, P kept in registers.
// ============================================================================
#define KPITCH 136                 // halfs (128 + 8 pad -> 272B)
#define KST    (64 * KPITCH)

__global__ __launch_bounds__(256, 1) void flash_attn() {
    extern __shared__ __half sm[];
    __half* Ks = sm;               // [2][64][KPITCH]
    __half* Vs = sm + 2 * KST;     // [2][64][KPITCH]

    const int bh = blockIdx.y;
    const int q0 = blockIdx.x * 128;
    const __half* Qg = g_Q + (size_t)bh * S_LEN * DK;
    const __half* Kg = g_K + (size_t)bh * S_LEN * DK;
    const __half* Vg = g_V + (size_t)bh * S_LEN * DK;

    const int tid = threadIdx.x;
    const int warp = tid >> 5, lane = tid & 31;
    const int la3 = lane & 3, lg = lane >> 2;

    // ---- Q fragments straight into registers ----
    uint32_t qf[8][4];
    {
        const __half* Q0 = Qg + (size_t)(q0 + warp * 16 + lg) * DK + la3 * 2;
#pragma unroll
        for (int kk = 0; kk < 8; kk++) {
            qf[kk][0] = *(const uint32_t*)&Q0[kk * 16];
            qf[kk][1] = *(const uint32_t*)&Q0[8 * DK + kk * 16];
            qf[kk][2] = *(const uint32_t*)&Q0[kk * 16 + 8];
            qf[kk][3] = *(const uint32_t*)&Q0[8 * DK + kk * 16 + 8];
        }
    }

    auto loadKV = [&](int s, int k0) {
        __half* ks = Ks + s * KST;
        __half* vs = Vs + s * KST;
        // 64 rows x 16 chunks(8 halfs) = 1024 per tensor ; 4 per thread
#pragma unroll
        for (int p = 0; p < 4; p++) {
            int i = tid + p * 256;
            int r = i >> 4, c8 = (i & 15) * 8;
            cp16(ks + r * KPITCH + c8, &Kg[(size_t)(k0 + r) * DK + c8]);
            cp16(vs + r * KPITCH + c8, &Vg[(size_t)(k0 + r) * DK + c8]);
        }
    };

    float m_prev0 = -1e30f, m_prev1 = -1e30f;
    float l0 = 0.f, l1 = 0.f;
    float o[16][4];
#pragma unroll
    for (int nf = 0; nf < 16; nf++)
#pragma unroll
        for (int e = 0; e < 4; e++) o[nf][e] = 0.f;

    const int qrow0 = q0 + warp * 16 + lg;
    const int warp_qmax = q0 + warp * 16 + 15;
    const int nkt = blockIdx.x * 2 + 2;
    const float sc = 0.08838834764831845f;   // 1/sqrt(128)

    const int b_row = (lane & 7) + ((lane >> 4) & 1) * 8;
    const int b_col = ((lane >> 3) & 1) * 8;
    const int v_row = lane & 15;            // trans: rows = key dim
    const int v_col = (lane >> 4) * 8;

    loadKV(0, 0);
    cp_commit();

    for (int kt = 0; kt < nkt; kt++) {
        const int k0 = kt * 64;
        if (kt + 1 < nkt) {
            loadKV((kt + 1) & 1, (kt + 1) * 64);
            cp_commit();
            cp_wait<1>();
        } else {
            cp_wait<0>();
        }
        __syncthreads();

        const int st = kt & 1;
        const __half* ks = Ks + st * KST;
        const __half* vs = Vs + st * KST;

        if (k0 <= warp_qmax) {
            // ---- S = Q K^T  (16 x 64 per warp) ----
            float s[8][4];
#pragma unroll
            for (int nf = 0; nf < 8; nf++)
#pragma unroll
                for (int e = 0; e < 4; e++) s[nf][e] = 0.f;

#pragma unroll
            for (int kk = 0; kk < 8; kk++) {
                uint32_t bf[8][2];
#pragma unroll
                for (int j = 0; j < 4; j++) {
                    uint32_t r0, r1, r2, r3;
                    ldsm4(r0, r1, r2, r3,
                          ks + (j * 16 + b_row) * KPITCH + kk * 16 + b_col);
                    bf[2 * j][0] = r0; bf[2 * j][1] = r1;
                    bf[2 * j + 1][0] = r2; bf[2 * j + 1][1] = r3;
                }
#pragma unroll
                for (int nf = 0; nf < 8; nf++) mma_f16(s[nf], qf[kk], bf[nf]);
            }

            // ---- scale + causal mask + running softmax ----
            float mx0 = -1e30f, mx1 = -1e30f;
#pragma unroll
            for (int nf = 0; nf < 8; nf++)
#pragma unroll
                for (int e = 0; e < 4; e++) {
                    int col = k0 + nf * 8 + la3 * 2 + (e & 1);
                    int qr  = qrow0 + ((e >= 2) ? 8 : 0);
                    float v = s[nf][e] * sc;
                    if (col > qr) v = -1e30f;
                    s[nf][e] = v;
                    if (e < 2) { mx0 = fmaxf(mx0, v); } else { mx1 = fmaxf(mx1, v); }
                }
            mx0 = fmaxf(mx0, __shfl_xor_sync(0xffffffff, mx0, 1));
            mx0 = fmaxf(mx0, __shfl_xor_sync(0xffffffff, mx0, 2));
            mx1 = fmaxf(mx1, __shfl_xor_sync(0xffffffff, mx1, 1));
            mx1 = fmaxf(mx1, __shfl_xor_sync(0xffffffff, mx1, 2));

            float mn0 = fmaxf(m_prev0, mx0);
            float mn1 = fmaxf(m_prev1, mx1);

            float sum0 = 0.f, sum1 = 0.f;
#pragma unroll
            for (int nf = 0; nf < 8; nf++)
#pragma unroll
                for (int e = 0; e < 4; e++) {
                    float p = __expf(s[nf][e] - ((e < 2) ? mn0 : mn1));
                    s[nf][e] = p;
                    if (e < 2) sum0 += p; else sum1 += p;
                }
            sum0 += __shfl_xor_sync(0xffffffff, sum0, 1);
            sum0 += __shfl_xor_sync(0xffffffff, sum0, 2);
            sum1 += __shfl_xor_sync(0xffffffff, sum1, 1);
            sum1 += __shfl_xor_sync(0xffffffff, sum1, 2);

            float corr0 = __expf(m_prev0 - mn0);
            float corr1 = __expf(m_prev1 - mn1);
            l0 = l0 * corr0 + sum0;
            l1 = l1 * corr1 + sum1;
            m_prev0 = mn0; m_prev1 = mn1;

#pragma unroll
            for (int nf = 0; nf < 16; nf++) {
                o[nf][0] *= corr0; o[nf][1] *= corr0;
                o[nf][2] *= corr1; o[nf][3] *= corr1;
            }

            // ---- pack P into A-fragments (registers only) ----
            uint32_t ph[4][4];
#pragma unroll
            for (int kk2 = 0; kk2 < 4; kk2++) {
                __half2 h;
                h = __floats2half2_rn(s[2 * kk2][0], s[2 * kk2][1]);     ph[kk2][0] = *(uint32_t*)&h;
                h = __floats2half2_rn(s[2 * kk2][2], s[2 * kk2][3]);     ph[kk2][1] = *(uint32_t*)&h;
                h = __floats2half2_rn(s[2 * kk2 + 1][0], s[2 * kk2 + 1][1]); ph[kk2][2] = *(uint32_t*)&h;
                h = __floats2half2_rn(s[2 * kk2 + 1][2], s[2 * kk2 + 1][3]); ph[kk2][3] = *(uint32_t*)&h;
            }

            // ---- O += P V  (16 x 128 per warp) ----
#pragma unroll
            for (int kk2 = 0; kk2 < 4; kk2++) {
#pragma unroll
                for (int j = 0; j < 8; j++) {
                    uint32_t r0, r1, r2, r3;
                    ldsm4t(r0, r1, r2, r3,
                           vs + (kk2 * 16 + v_row) * KPITCH + j * 16 + v_col);
                    uint32_t bf0[2] = {r0, r1};
                    uint32_t bf1[2] = {r2, r3};
                    mma_f16(o[2 * j], ph[kk2], bf0);
                    mma_f16(o[2 * j + 1], ph[kk2], bf1);
                }
            }
        }
        __syncthreads();
    }

    // ---- epilogue: normalize, fp16-round, write [b, s, h*DK + v] ----
    const int b = bh >> 4, h = bh & 15;
    float inv0 = 1.f / l0, inv1 = 1.f / l1;
#pragma unroll
    for (int nf = 0; nf < 16; nf++)
#pragma unroll
        for (int ep = 0; ep < 2; ep++) {
            int q = qrow0 + ep * 8;
            int v = nf * 8 + la3 * 2;
            float inv = ep ? inv1 : inv0;
            __half2 h2 = __floats2half2_rn(o[nf][2 * ep] * inv, o[nf][2 * ep + 1] * inv);
            *(__half2*)&g_Attn[((size_t)b * S_LEN + q) * DM + h * DK + v] = h2;
        }
}

// ============================================================================
// launch
// ============================================================================
extern "C" void kernel_launch(void* const* d_in, const int* in_sizes, int n_in,
                              void* d_out, int out_size) {
    const float* x  = (const float*)d_in[0];
    const float* WQ = (const float*)d_in[1];
    const float* WK = (const float*)d_in[2];
    const float* WV = (const float*)d_in[3];
    const float* WO = (const float*)d_in[4];
    float* out = (float*)d_out;

    __half *pQ, *pK, *pV, *pA, *pXh, *pWh;
    cudaGetSymbolAddress((void**)&pQ,  g_Q);
    cudaGetSymbolAddress((void**)&pK,  g_K);
    cudaGetSymbolAddress((void**)&pV,  g_V);
    cudaGetSymbolAddress((void**)&pA,  g_Attn);
    cudaGetSymbolAddress((void**)&pXh, g_xh);
    cudaGetSymbolAddress((void**)&pWh, g_Wh);

    const size_t WSZ = (size_t)DM * DM;
    const int gemm_smem  = STG * (A_ST + B_ST) * 2;     // 122880
    const int flash_smem = 4 * KST * 2;                 // 69632
    cudaFuncSetAttribute(gemm_nt<0>, cudaFuncAttributeMaxDynamicSharedMemorySize, gemm_smem);
    cudaFuncSetAttribute(gemm_nt<1>, cudaFuncAttributeMaxDynamicSharedMemorySize, gemm_smem);
    cudaFuncSetAttribute(flash_attn, cudaFuncAttributeMaxDynamicSharedMemorySize, flash_smem);

    cvt_f16<<<1024, 256>>>(x,  pXh,           (NB * S_LEN * DM) / 4);
    cvt_f16<<<512,  256>>>(WQ, pWh + 0 * WSZ, (int)(WSZ / 4));
    cvt_f16<<<512,  256>>>(WK, pWh + 1 * WSZ, (int)(WSZ / 4));
    cvt_f16<<<512,  256>>>(WV, pWh + 2 * WSZ, (int)(WSZ / 4));
    cvt_f16<<<512,  256>>>(WO, pWh + 3 * WSZ, (int)(WSZ / 4));

    dim3 ggrid(16, 32);   // N/128, M/256
    dim3 gblk(512);
    gemm_nt<1><<<ggrid, gblk, gemm_smem>>>(pXh, pWh + 0 * WSZ, pQ);
    gemm_nt<1><<<ggrid, gblk, gemm_smem>>>(pXh, pWh + 1 * WSZ, pK);
    gemm_nt<1><<<ggrid, gblk, gemm_smem>>>(pXh, pWh + 2 * WSZ, pV);

    dim3 fgrid(16, 64);   // S/128 q-tiles, B*H
    flash_attn<<<fgrid, 256, flash_smem>>>();

    gemm_nt<0><<<ggrid, gblk, gemm_smem>>>(pA, pWh + 3 * WSZ, out);
}

// round 5
// speedup vs baseline: 2.7555x; 1.1904x over previous
#include <cuda_runtime.h>
#include <cuda_fp16.h>
#include <cstdint>

#define S_LEN 2048
#define DM    2048
#define NH    16
#define DK    128
#define NB    4

// -------- scratch (static __device__ arrays) --------
__device__ __half g_Q[(size_t)NB * NH * S_LEN * DK];    // [b,h,s,dk] fp16
__device__ __half g_K[(size_t)NB * NH * S_LEN * DK];
__device__ __half g_V[(size_t)NB * NH * S_LEN * DK];
__device__ __half g_Attn[(size_t)NB * S_LEN * DM];      // [b,s,h*DK+v] fp16
__device__ __half g_xh[(size_t)NB * S_LEN * DM];        // x fp16
__device__ __half g_Wh[4][(size_t)DM * DM];             // weights fp16

// -------- helpers --------
__device__ __forceinline__ void mma_f16(float c[4], const uint32_t a[4], const uint32_t b[2]) {
    asm volatile(
        "mma.sync.aligned.m16n8k16.row.col.f32.f16.f16.f32 "
        "{%0,%1,%2,%3}, {%4,%5,%6,%7}, {%8,%9}, {%0,%1,%2,%3};"
        : "+f"(c[0]), "+f"(c[1]), "+f"(c[2]), "+f"(c[3])
        : "r"(a[0]), "r"(a[1]), "r"(a[2]), "r"(a[3]), "r"(b[0]), "r"(b[1]));
}

__device__ __forceinline__ void ldsm4(uint32_t& r0, uint32_t& r1, uint32_t& r2, uint32_t& r3,
                                      const void* p) {
    uint32_t a = (uint32_t)__cvta_generic_to_shared(p);
    asm volatile("ldmatrix.sync.aligned.m8n8.x4.shared.b16 {%0,%1,%2,%3}, [%4];"
                 : "=r"(r0), "=r"(r1), "=r"(r2), "=r"(r3) : "r"(a));
}
__device__ __forceinline__ void ldsm4t(uint32_t& r0, uint32_t& r1, uint32_t& r2, uint32_t& r3,
                                       const void* p) {
    uint32_t a = (uint32_t)__cvta_generic_to_shared(p);
    asm volatile("ldmatrix.sync.aligned.m8n8.x4.trans.shared.b16 {%0,%1,%2,%3}, [%4];"
                 : "=r"(r0), "=r"(r1), "=r"(r2), "=r"(r3) : "r"(a));
}

__device__ __forceinline__ void cp16(void* sptr, const void* g) {
    uint32_t sa = (uint32_t)__cvta_generic_to_shared(sptr);
    asm volatile("cp.async.cg.shared.global [%0], [%1], 16;" :: "r"(sa), "l"(g));
}
__device__ __forceinline__ void cp_commit() { asm volatile("cp.async.commit_group;"); }
template <int N>
__device__ __forceinline__ void cp_wait() { asm volatile("cp.async.wait_group %0;" :: "n"(N)); }

// ============================================================================
// fused f32 -> f16 conversion: grid.y picks a slice (0-3: quarters of x, 4-7: weights)
// ============================================================================
__global__ void cvt_all(const float* __restrict__ x,
                        const float* __restrict__ w0, const float* __restrict__ w1,
                        const float* __restrict__ w2, const float* __restrict__ w3,
                        __half* __restrict__ xh, __half* __restrict__ wh) {
    const int seg = blockIdx.y;
    const size_t WSZ = (size_t)DM * DM;
    const size_t n4 = WSZ / 4;     // 1048576 float4 per segment
    const float* in;
    __half* out;
    if (seg < 4)      { in = x + seg * WSZ;  out = xh + seg * WSZ; }
    else if (seg == 4){ in = w0;             out = wh + 0 * WSZ; }
    else if (seg == 5){ in = w1;             out = wh + 1 * WSZ; }
    else if (seg == 6){ in = w2;             out = wh + 2 * WSZ; }
    else              { in = w3;             out = wh + 3 * WSZ; }

    size_t i = blockIdx.x * blockDim.x + threadIdx.x;
    size_t st = (size_t)gridDim.x * blockDim.x;
    for (; i < n4; i += st) {
        float4 v = ((const float4*)in)[i];
        __half2 h0 = __floats2half2_rn(v.x, v.y);
        __half2 h1 = __floats2half2_rn(v.z, v.w);
        uint2 u;
        u.x = *(uint32_t*)&h0; u.y = *(uint32_t*)&h1;
        ((uint2*)out)[i] = u;
    }
}

// ============================================================================
// NT GEMM (fp16 in, fp32 acc): C[8192,2048] = A[8192,2048] * W[2048,2048]^T
// Tile 128x128, 256 thr (8 warps 4x2), warp 32x64, BK=32, 4-stage cp.async,
// 2 CTAs/SM. MODE 1: gridDim.z=3 -> QKV, scatter half [b,h,s,dk].
// MODE 0: single W, float row-major out.
// ============================================================================
#define BK     32
#define APITCH 40                  // halfs per row (32 + 8 pad)
#define STG    4
#define T_ST   (128 * APITCH)      // halfs per stage per tensor
#define GEMM_SMEM (STG * T_ST * 2 * 2)   // 81920 bytes

template <int MODE>
__global__ __launch_bounds__(256, 2) void gemm_nt(const __half* __restrict__ A,
                                                  const __half* __restrict__ Wb,
                                                  void* C0, void* C1, void* C2) {
    extern __shared__ __half sm[];
    __half* As = sm;                 // [STG][128][APITCH]
    __half* Bs = sm + STG * T_ST;    // [STG][128][APITCH]

    const int z = blockIdx.z;
    const __half* Bw = (MODE == 1) ? Wb + (size_t)z * DM * DM : Wb;
    void* Cv = (MODE == 1) ? (z == 0 ? C0 : (z == 1 ? C1 : C2)) : C0;

    const int m0 = blockIdx.y * 128;
    const int n0 = blockIdx.x * 128;
    const int tid = threadIdx.x;
    const int warp = tid >> 5, lane = tid & 31;
    const int wm = warp >> 1, wn = warp & 1;     // 4 x 2 warps
    const int la3 = lane & 3, lg = lane >> 2;

    float acc[2][8][4];
#pragma unroll
    for (int i = 0; i < 2; i++)
#pragma unroll
        for (int j = 0; j < 8; j++)
#pragma unroll
            for (int e = 0; e < 4; e++) acc[i][j][e] = 0.f;

    auto loadStage = [&](int s, int k0) {
        __half* as = As + s * T_ST;
        __half* bs = Bs + s * T_ST;
        // 128 rows x 4 chunks(8 halfs) = 512 per tensor ; 2 per thread each
#pragma unroll
        for (int p = 0; p < 2; p++) {
            int i = tid + p * 256;
            int r = i >> 2, c8 = (i & 3) * 8;
            cp16(as + r * APITCH + c8, &A[(size_t)(m0 + r) * 2048 + k0 + c8]);
            cp16(bs + r * APITCH + c8, &Bw[(size_t)(n0 + r) * 2048 + k0 + c8]);
        }
    };

#pragma unroll
    for (int s = 0; s < STG - 1; s++) { loadStage(s, s * BK); cp_commit(); }

    const int a_row = lane & 15, a_col = (lane >> 4) * 8;
    const int b_row = (lane & 7) + ((lane >> 4) & 1) * 8;
    const int b_col = ((lane >> 3) & 1) * 8;

    const int NCH = 2048 / BK;
    for (int ch = 0; ch < NCH; ch++) {
        cp_wait<STG - 2>();
        __syncthreads();
        int pre = ch + STG - 1;
        if (pre < NCH) loadStage(pre & (STG - 1), pre * BK);
        cp_commit();

        const __half* as = As + (ch & (STG - 1)) * T_ST;
        const __half* bs = Bs + (ch & (STG - 1)) * T_ST;
#pragma unroll
        for (int kk = 0; kk < 2; kk++) {
            uint32_t af[2][4], bf[8][2];
#pragma unroll
            for (int mf = 0; mf < 2; mf++)
                ldsm4(af[mf][0], af[mf][1], af[mf][2], af[mf][3],
                      as + (wm * 32 + mf * 16 + a_row) * APITCH + kk * 16 + a_col);
#pragma unroll
            for (int j = 0; j < 4; j++) {
                uint32_t r0, r1, r2, r3;
                ldsm4(r0, r1, r2, r3,
                      bs + (wn * 64 + j * 16 + b_row) * APITCH + kk * 16 + b_col);
                bf[2 * j][0] = r0; bf[2 * j][1] = r1;
                bf[2 * j + 1][0] = r2; bf[2 * j + 1][1] = r3;
            }
#pragma unroll
            for (int mf = 0; mf < 2; mf++)
#pragma unroll
                for (int nf = 0; nf < 8; nf++) mma_f16(acc[mf][nf], af[mf], bf[nf]);
        }
    }

#pragma unroll
    for (int mf = 0; mf < 2; mf++)
#pragma unroll
        for (int nf = 0; nf < 8; nf++)
#pragma unroll
            for (int ep = 0; ep < 2; ep++) {
                int r = m0 + wm * 32 + mf * 16 + lg + ep * 8;
                int c = n0 + wn * 64 + nf * 8 + la3 * 2;
                float v0 = acc[mf][nf][2 * ep], v1 = acc[mf][nf][2 * ep + 1];
                if (MODE == 0) {
                    float2 f2 = make_float2(v0, v1);
                    *(float2*)&((float*)Cv)[(size_t)r * 2048 + c] = f2;
                } else {
                    int b = r >> 11, s = r & 2047;
                    int h = c >> 7, d = c & 127;
                    __half2 h2 = __floats2half2_rn(v0, v1);
                    *(__half2*)&((__half*)Cv)[((((size_t)b * NH) + h) * S_LEN + s) * DK + d] = h2;
                }
            }
}

// ============================================================================
// Flash attention (causal, fp16).  Block = 128 q-rows of one (b,h), 256 thr.
// Q in registers, K/V double-buffered cp.async, P in registers.
// Heavy q-blocks scheduled first (reversed blockIdx.x).
// ============================================================================
#define KPITCH 136                 // halfs (128 + 8 pad)
#define KST    (64 * KPITCH)

__global__ __launch_bounds__(256, 1) void flash_attn() {
    extern __shared__ __half sm[];
    __half* Ks = sm;               // [2][64][KPITCH]
    __half* Vs = sm + 2 * KST;

    const int bh = blockIdx.y;
    const int qblk = gridDim.x - 1 - blockIdx.x;     // heavy-first
    const int q0 = qblk * 128;
    const __half* Qg = g_Q + (size_t)bh * S_LEN * DK;
    const __half* Kg = g_K + (size_t)bh * S_LEN * DK;
    const __half* Vg = g_V + (size_t)bh * S_LEN * DK;

    const int tid = threadIdx.x;
    const int warp = tid >> 5, lane = tid & 31;
    const int la3 = lane & 3, lg = lane >> 2;

    uint32_t qf[8][4];
    {
        const __half* Q0 = Qg + (size_t)(q0 + warp * 16 + lg) * DK + la3 * 2;
#pragma unroll
        for (int kk = 0; kk < 8; kk++) {
            qf[kk][0] = *(const uint32_t*)&Q0[kk * 16];
            qf[kk][1] = *(const uint32_t*)&Q0[8 * DK + kk * 16];
            qf[kk][2] = *(const uint32_t*)&Q0[kk * 16 + 8];
            qf[kk][3] = *(const uint32_t*)&Q0[8 * DK + kk * 16 + 8];
        }
    }

    auto loadKV = [&](int s, int k0) {
        __half* ks = Ks + s * KST;
        __half* vs = Vs + s * KST;
#pragma unroll
        for (int p = 0; p < 4; p++) {
            int i = tid + p * 256;
            int r = i >> 4, c8 = (i & 15) * 8;
            cp16(ks + r * KPITCH + c8, &Kg[(size_t)(k0 + r) * DK + c8]);
            cp16(vs + r * KPITCH + c8, &Vg[(size_t)(k0 + r) * DK + c8]);
        }
    };

    float m_prev0 = -1e30f, m_prev1 = -1e30f;
    float l0 = 0.f, l1 = 0.f;
    float o[16][4];
#pragma unroll
    for (int nf = 0; nf < 16; nf++)
#pragma unroll
        for (int e = 0; e < 4; e++) o[nf][e] = 0.f;

    const int qrow0 = q0 + warp * 16 + lg;
    const int warp_qmax = q0 + warp * 16 + 15;
    const int nkt = qblk * 2 + 2;
    const float sc = 0.08838834764831845f;   // 1/sqrt(128)

    const int b_row = (lane & 7) + ((lane >> 4) & 1) * 8;
    const int b_col = ((lane >> 3) & 1) * 8;
    const int v_row = lane & 15;
    const int v_col = (lane >> 4) * 8;

    loadKV(0, 0);
    cp_commit();

    for (int kt = 0; kt < nkt; kt++) {
        const int k0 = kt * 64;
        if (kt + 1 < nkt) {
            loadKV((kt + 1) & 1, (kt + 1) * 64);
            cp_commit();
            cp_wait<1>();
        } else {
            cp_wait<0>();
        }
        __syncthreads();

        const int st = kt & 1;
        const __half* ks = Ks + st * KST;
        const __half* vs = Vs + st * KST;

        if (k0 <= warp_qmax) {
            float s[8][4];
#pragma unroll
            for (int nf = 0; nf < 8; nf++)
#pragma unroll
                for (int e = 0; e < 4; e++) s[nf][e] = 0.f;

#pragma unroll
            for (int kk = 0; kk < 8; kk++) {
                uint32_t bf[8][2];
#pragma unroll
                for (int j = 0; j < 4; j++) {
                    uint32_t r0, r1, r2, r3;
                    ldsm4(r0, r1, r2, r3,
                          ks + (j * 16 + b_row) * KPITCH + kk * 16 + b_col);
                    bf[2 * j][0] = r0; bf[2 * j][1] = r1;
                    bf[2 * j + 1][0] = r2; bf[2 * j + 1][1] = r3;
                }
#pragma unroll
                for (int nf = 0; nf < 8; nf++) mma_f16(s[nf], qf[kk], bf[nf]);
            }

            float mx0 = -1e30f, mx1 = -1e30f;
#pragma unroll
            for (int nf = 0; nf < 8; nf++)
#pragma unroll
                for (int e = 0; e < 4; e++) {
                    int col = k0 + nf * 8 + la3 * 2 + (e & 1);
                    int qr  = qrow0 + ((e >= 2) ? 8 : 0);
                    float v = s[nf][e] * sc;
                    if (col > qr) v = -1e30f;
                    s[nf][e] = v;
                    if (e < 2) { mx0 = fmaxf(mx0, v); } else { mx1 = fmaxf(mx1, v); }
                }
            mx0 = fmaxf(mx0, __shfl_xor_sync(0xffffffff, mx0, 1));
            mx0 = fmaxf(mx0, __shfl_xor_sync(0xffffffff, mx0, 2));
            mx1 = fmaxf(mx1, __shfl_xor_sync(0xffffffff, mx1, 1));
            mx1 = fmaxf(mx1, __shfl_xor_sync(0xffffffff, mx1, 2));

            float mn0 = fmaxf(m_prev0, mx0);
            float mn1 = fmaxf(m_prev1, mx1);

            float sum0 = 0.f, sum1 = 0.f;
#pragma unroll
            for (int nf = 0; nf < 8; nf++)
#pragma unroll
                for (int e = 0; e < 4; e++) {
                    float p = __expf(s[nf][e] - ((e < 2) ? mn0 : mn1));
                    s[nf][e] = p;
                    if (e < 2) sum0 += p; else sum1 += p;
                }
            sum0 += __shfl_xor_sync(0xffffffff, sum0, 1);
            sum0 += __shfl_xor_sync(0xffffffff, sum0, 2);
            sum1 += __shfl_xor_sync(0xffffffff, sum1, 1);
            sum1 += __shfl_xor_sync(0xffffffff, sum1, 2);

            float corr0 = __expf(m_prev0 - mn0);
            float corr1 = __expf(m_prev1 - mn1);
            l0 = l0 * corr0 + sum0;
            l1 = l1 * corr1 + sum1;
            m_prev0 = mn0; m_prev1 = mn1;

#pragma unroll
            for (int nf = 0; nf < 16; nf++) {
                o[nf][0] *= corr0; o[nf][1] *= corr0;
                o[nf][2] *= corr1; o[nf][3] *= corr1;
            }

            uint32_t ph[4][4];
#pragma unroll
            for (int kk2 = 0; kk2 < 4; kk2++) {
                __half2 h;
                h = __floats2half2_rn(s[2 * kk2][0], s[2 * kk2][1]);         ph[kk2][0] = *(uint32_t*)&h;
                h = __floats2half2_rn(s[2 * kk2][2], s[2 * kk2][3]);         ph[kk2][1] = *(uint32_t*)&h;
                h = __floats2half2_rn(s[2 * kk2 + 1][0], s[2 * kk2 + 1][1]); ph[kk2][2] = *(uint32_t*)&h;
                h = __floats2half2_rn(s[2 * kk2 + 1][2], s[2 * kk2 + 1][3]); ph[kk2][3] = *(uint32_t*)&h;
            }

#pragma unroll
            for (int kk2 = 0; kk2 < 4; kk2++) {
#pragma unroll
                for (int j = 0; j < 8; j++) {
                    uint32_t r0, r1, r2, r3;
                    ldsm4t(r0, r1, r2, r3,
                           vs + (kk2 * 16 + v_row) * KPITCH + j * 16 + v_col);
                    uint32_t bf0[2] = {r0, r1};
                    uint32_t bf1[2] = {r2, r3};
                    mma_f16(o[2 * j], ph[kk2], bf0);
                    mma_f16(o[2 * j + 1], ph[kk2], bf1);
                }
            }
        }
        __syncthreads();
    }

    const int b = bh >> 4, h = bh & 15;
    float inv0 = 1.f / l0, inv1 = 1.f / l1;
#pragma unroll
    for (int nf = 0; nf < 16; nf++)
#pragma unroll
        for (int ep = 0; ep < 2; ep++) {
            int q = qrow0 + ep * 8;
            int v = nf * 8 + la3 * 2;
            float inv = ep ? inv1 : inv0;
            __half2 h2 = __floats2half2_rn(o[nf][2 * ep] * inv, o[nf][2 * ep + 1] * inv);
            *(__half2*)&g_Attn[((size_t)b * S_LEN + q) * DM + h * DK + v] = h2;
        }
}

// ============================================================================
// launch
// ============================================================================
extern "C" void kernel_launch(void* const* d_in, const int* in_sizes, int n_in,
                              void* d_out, int out_size) {
    const float* x  = (const float*)d_in[0];
    const float* WQ = (const float*)d_in[1];
    const float* WK = (const float*)d_in[2];
    const float* WV = (const float*)d_in[3];
    const float* WO = (const float*)d_in[4];
    float* out = (float*)d_out;

    __half *pQ, *pK, *pV, *pA, *pXh, *pWh;
    cudaGetSymbolAddress((void**)&pQ,  g_Q);
    cudaGetSymbolAddress((void**)&pK,  g_K);
    cudaGetSymbolAddress((void**)&pV,  g_V);
    cudaGetSymbolAddress((void**)&pA,  g_Attn);
    cudaGetSymbolAddress((void**)&pXh, g_xh);
    cudaGetSymbolAddress((void**)&pWh, g_Wh);

    const size_t WSZ = (size_t)DM * DM;
    const int flash_smem = 4 * KST * 2;                 // 69632
    cudaFuncSetAttribute(gemm_nt<0>, cudaFuncAttributeMaxDynamicSharedMemorySize, GEMM_SMEM);
    cudaFuncSetAttribute(gemm_nt<1>, cudaFuncAttributeMaxDynamicSharedMemorySize, GEMM_SMEM);
    cudaFuncSetAttribute(flash_attn, cudaFuncAttributeMaxDynamicSharedMemorySize, flash_smem);

    // one fused conversion launch: 8 equal slices (4x quarters of x, 4 weights)
    cvt_all<<<dim3(96, 8), 256>>>(x, WQ, WK, WV, WO, pXh, pWh);

    // fused QKV projection: gridDim.z selects weight/output
    dim3 qkv_grid(16, 64, 3);   // N/128, M/128, {Q,K,V}
    gemm_nt<1><<<qkv_grid, 256, GEMM_SMEM>>>(pXh, pWh, pQ, pK, pV);

    dim3 fgrid(16, 64);
    flash_attn<<<fgrid, 256, flash_smem>>>();

    dim3 o_grid(16, 64, 1);
    gemm_nt<0><<<o_grid, 256, GEMM_SMEM>>>(pA, pWh + 3 * WSZ, out, nullptr, nullptr);
}

// round 6
// speedup vs baseline: 3.0085x; 1.0918x over previous
#include <cuda_runtime.h>
#include <cuda_fp16.h>
#include <cstdint>

#define S_LEN 2048
#define DM    2048
#define NH    16
#define DK    128
#define NB    4

// -------- scratch (static __device__ arrays) --------
__device__ __half g_Q[(size_t)NB * NH * S_LEN * DK];    // [b,h,s,dk] fp16
__device__ __half g_K[(size_t)NB * NH * S_LEN * DK];
__device__ __half g_V[(size_t)NB * NH * S_LEN * DK];
__device__ __half g_Attn[(size_t)NB * S_LEN * DM];      // [b,s,h*DK+v] fp16
__device__ __half g_xh[(size_t)NB * S_LEN * DM];        // x fp16
__device__ __half g_Wh[4][(size_t)DM * DM];             // weights fp16

// -------- helpers --------
__device__ __forceinline__ void mma_f16(float c[4], const uint32_t a[4], const uint32_t b[2]) {
    asm volatile(
        "mma.sync.aligned.m16n8k16.row.col.f32.f16.f16.f32 "
        "{%0,%1,%2,%3}, {%4,%5,%6,%7}, {%8,%9}, {%0,%1,%2,%3};"
        : "+f"(c[0]), "+f"(c[1]), "+f"(c[2]), "+f"(c[3])
        : "r"(a[0]), "r"(a[1]), "r"(a[2]), "r"(a[3]), "r"(b[0]), "r"(b[1]));
}

__device__ __forceinline__ void ldsm4(uint32_t& r0, uint32_t& r1, uint32_t& r2, uint32_t& r3,
                                      const void* p) {
    uint32_t a = (uint32_t)__cvta_generic_to_shared(p);
    asm volatile("ldmatrix.sync.aligned.m8n8.x4.shared.b16 {%0,%1,%2,%3}, [%4];"
                 : "=r"(r0), "=r"(r1), "=r"(r2), "=r"(r3) : "r"(a));
}
__device__ __forceinline__ void ldsm4t(uint32_t& r0, uint32_t& r1, uint32_t& r2, uint32_t& r3,
                                       const void* p) {
    uint32_t a = (uint32_t)__cvta_generic_to_shared(p);
    asm volatile("ldmatrix.sync.aligned.m8n8.x4.trans.shared.b16 {%0,%1,%2,%3}, [%4];"
                 : "=r"(r0), "=r"(r1), "=r"(r2), "=r"(r3) : "r"(a));
}

__device__ __forceinline__ void cp16(void* sptr, const void* g) {
    uint32_t sa = (uint32_t)__cvta_generic_to_shared(sptr);
    asm volatile("cp.async.cg.shared.global [%0], [%1], 16;" :: "r"(sa), "l"(g));
}
__device__ __forceinline__ void cp_commit() { asm volatile("cp.async.commit_group;"); }
template <int N>
__device__ __forceinline__ void cp_wait() { asm volatile("cp.async.wait_group %0;" :: "n"(N)); }

// ============================================================================
// fused f32 -> f16 conversion: grid.y picks a slice (0-3: quarters of x, 4-7: weights)
// ============================================================================
__global__ void cvt_all(const float* __restrict__ x,
                        const float* __restrict__ w0, const float* __restrict__ w1,
                        const float* __restrict__ w2, const float* __restrict__ w3,
                        __half* __restrict__ xh, __half* __restrict__ wh) {
    const int seg = blockIdx.y;
    const size_t WSZ = (size_t)DM * DM;
    const size_t n4 = WSZ / 4;
    const float* in;
    __half* out;
    if (seg < 4)      { in = x + seg * WSZ;  out = xh + seg * WSZ; }
    else if (seg == 4){ in = w0;             out = wh + 0 * WSZ; }
    else if (seg == 5){ in = w1;             out = wh + 1 * WSZ; }
    else if (seg == 6){ in = w2;             out = wh + 2 * WSZ; }
    else              { in = w3;             out = wh + 3 * WSZ; }

    size_t i = blockIdx.x * blockDim.x + threadIdx.x;
    size_t st = (size_t)gridDim.x * blockDim.x;
    for (; i < n4; i += st) {
        float4 v = ((const float4*)in)[i];
        __half2 h0 = __floats2half2_rn(v.x, v.y);
        __half2 h1 = __floats2half2_rn(v.z, v.w);
        uint2 u;
        u.x = *(uint32_t*)&h0; u.y = *(uint32_t*)&h1;
        ((uint2*)out)[i] = u;
    }
}

// ============================================================================
// NT GEMM (fp16 in, fp32 acc): C[8192,2048] = A[8192,2048] * W[2048,2048]^T
// Tile 128x128, 256 thr (8 warps 4x2), warp 32x64, BK=64, 3-stage cp.async,
// 2 CTAs/SM. One __syncthreads per 64-MMA chunk.
// MODE 1: gridDim.z=3 -> QKV, scatter half [b,h,s,dk].  MODE 0: float out.
// ============================================================================
#define BK     64
#define APITCH 72                  // halfs per row (64 + 8 pad = 144B = 36 words)
#define STG    3
#define T_ST   (128 * APITCH)      // halfs per stage per tensor
#define GEMM_SMEM (STG * T_ST * 2 * 2)   // 110592 bytes

template <int MODE>
__global__ __launch_bounds__(256, 2) void gemm_nt(const __half* __restrict__ A,
                                                  const __half* __restrict__ Wb,
                                                  void* C0, void* C1, void* C2) {
    extern __shared__ __half sm[];
    __half* As = sm;                 // [STG][128][APITCH]
    __half* Bs = sm + STG * T_ST;    // [STG][128][APITCH]

    const int z = blockIdx.z;
    const __half* Bw = (MODE == 1) ? Wb + (size_t)z * DM * DM : Wb;
    void* Cv = (MODE == 1) ? (z == 0 ? C0 : (z == 1 ? C1 : C2)) : C0;

    const int m0 = blockIdx.y * 128;
    const int n0 = blockIdx.x * 128;
    const int tid = threadIdx.x;
    const int warp = tid >> 5, lane = tid & 31;
    const int wm = warp >> 1, wn = warp & 1;     // 4 x 2 warps
    const int la3 = lane & 3, lg = lane >> 2;

    float acc[2][8][4];
#pragma unroll
    for (int i = 0; i < 2; i++)
#pragma unroll
        for (int j = 0; j < 8; j++)
#pragma unroll
            for (int e = 0; e < 4; e++) acc[i][j][e] = 0.f;

    auto loadStage = [&](int s, int k0) {
        __half* as = As + s * T_ST;
        __half* bs = Bs + s * T_ST;
        // 128 rows x 8 chunks(8 halfs) per tensor = 1024 ; 4 per thread each
#pragma unroll
        for (int p = 0; p < 4; p++) {
            int i = tid + p * 256;
            int r = i >> 3, c8 = (i & 7) * 8;
            cp16(as + r * APITCH + c8, &A[(size_t)(m0 + r) * 2048 + k0 + c8]);
            cp16(bs + r * APITCH + c8, &Bw[(size_t)(n0 + r) * 2048 + k0 + c8]);
        }
        cp_commit();
    };

    loadStage(0, 0);
    loadStage(1, BK);

    const int a_row = lane & 15, a_col = (lane >> 4) * 8;
    const int b_row = (lane & 7) + ((lane >> 4) & 1) * 8;
    const int b_col = ((lane >> 3) & 1) * 8;

    const int NCH = 2048 / BK;    // 32
    int s = 0;                    // rotating stage index
    int sl = 2;                   // stage to load next
    for (int ch = 0; ch < NCH; ch++) {
        if (ch < NCH - 1) cp_wait<1>(); else cp_wait<0>();
        __syncthreads();
        if (ch <= NCH - 3) {
            loadStage(sl, (ch + 2) * BK);
            if (++sl == STG) sl = 0;
        }

        const __half* as = As + s * T_ST;
        const __half* bs = Bs + s * T_ST;
        if (++s == STG) s = 0;
#pragma unroll
        for (int kk = 0; kk < 4; kk++) {
            uint32_t af[2][4], bf[8][2];
#pragma unroll
            for (int mf = 0; mf < 2; mf++)
                ldsm4(af[mf][0], af[mf][1], af[mf][2], af[mf][3],
                      as + (wm * 32 + mf * 16 + a_row) * APITCH + kk * 16 + a_col);
#pragma unroll
            for (int j = 0; j < 4; j++) {
                uint32_t r0, r1, r2, r3;
                ldsm4(r0, r1, r2, r3,
                      bs + (wn * 64 + j * 16 + b_row) * APITCH + kk * 16 + b_col);
                bf[2 * j][0] = r0; bf[2 * j][1] = r1;
                bf[2 * j + 1][0] = r2; bf[2 * j + 1][1] = r3;
            }
#pragma unroll
            for (int mf = 0; mf < 2; mf++)
#pragma unroll
                for (int nf = 0; nf < 8; nf++) mma_f16(acc[mf][nf], af[mf], bf[nf]);
        }
    }

#pragma unroll
    for (int mf = 0; mf < 2; mf++)
#pragma unroll
        for (int nf = 0; nf < 8; nf++)
#pragma unroll
            for (int ep = 0; ep < 2; ep++) {
                int r = m0 + wm * 32 + mf * 16 + lg + ep * 8;
                int c = n0 + wn * 64 + nf * 8 + la3 * 2;
                float v0 = acc[mf][nf][2 * ep], v1 = acc[mf][nf][2 * ep + 1];
                if (MODE == 0) {
                    float2 f2 = make_float2(v0, v1);
                    *(float2*)&((float*)Cv)[(size_t)r * 2048 + c] = f2;
                } else {
                    int b = r >> 11, sq = r & 2047;
                    int h = c >> 7, d = c & 127;
                    __half2 h2 = __floats2half2_rn(v0, v1);
                    *(__half2*)&((__half*)Cv)[((((size_t)b * NH) + h) * S_LEN + sq) * DK + d] = h2;
                }
            }
}

// ============================================================================
// Flash attention (causal, fp16).  Block = 128 q-rows of one (b,h), 256 thr.
// Q in registers, K/V double-buffered cp.async, P in registers.
// Heavy q-blocks scheduled first (reversed blockIdx.x).
// ============================================================================
#define KPITCH 136                 // halfs (128 + 8 pad)
#define KST    (64 * KPITCH)

__global__ __launch_bounds__(256, 1) void flash_attn() {
    extern __shared__ __half sm[];
    __half* Ks = sm;               // [2][64][KPITCH]
    __half* Vs = sm + 2 * KST;

    const int bh = blockIdx.y;
    const int qblk = gridDim.x - 1 - blockIdx.x;     // heavy-first
    const int q0 = qblk * 128;
    const __half* Qg = g_Q + (size_t)bh * S_LEN * DK;
    const __half* Kg = g_K + (size_t)bh * S_LEN * DK;
    const __half* Vg = g_V + (size_t)bh * S_LEN * DK;

    const int tid = threadIdx.x;
    const int warp = tid >> 5, lane = tid & 31;
    const int la3 = lane & 3, lg = lane >> 2;

    uint32_t qf[8][4];
    {
        const __half* Q0 = Qg + (size_t)(q0 + warp * 16 + lg) * DK + la3 * 2;
#pragma unroll
        for (int kk = 0; kk < 8; kk++) {
            qf[kk][0] = *(const uint32_t*)&Q0[kk * 16];
            qf[kk][1] = *(const uint32_t*)&Q0[8 * DK + kk * 16];
            qf[kk][2] = *(const uint32_t*)&Q0[kk * 16 + 8];
            qf[kk][3] = *(const uint32_t*)&Q0[8 * DK + kk * 16 + 8];
        }
    }

    auto loadKV = [&](int s, int k0) {
        __half* ks = Ks + s * KST;
        __half* vs = Vs + s * KST;
#pragma unroll
        for (int p = 0; p < 4; p++) {
            int i = tid + p * 256;
            int r = i >> 4, c8 = (i & 15) * 8;
            cp16(ks + r * KPITCH + c8, &Kg[(size_t)(k0 + r) * DK + c8]);
            cp16(vs + r * KPITCH + c8, &Vg[(size_t)(k0 + r) * DK + c8]);
        }
    };

    float m_prev0 = -1e30f, m_prev1 = -1e30f;
    float l0 = 0.f, l1 = 0.f;
    float o[16][4];
#pragma unroll
    for (int nf = 0; nf < 16; nf++)
#pragma unroll
        for (int e = 0; e < 4; e++) o[nf][e] = 0.f;

    const int qrow0 = q0 + warp * 16 + lg;
    const int warp_qmax = q0 + warp * 16 + 15;
    const int nkt = qblk * 2 + 2;
    const float sc = 0.08838834764831845f;   // 1/sqrt(128)

    const int b_row = (lane & 7) + ((lane >> 4) & 1) * 8;
    const int b_col = ((lane >> 3) & 1) * 8;
    const int v_row = lane & 15;
    const int v_col = (lane >> 4) * 8;

    loadKV(0, 0);
    cp_commit();

    for (int kt = 0; kt < nkt; kt++) {
        const int k0 = kt * 64;
        if (kt + 1 < nkt) {
            loadKV((kt + 1) & 1, (kt + 1) * 64);
            cp_commit();
            cp_wait<1>();
        } else {
            cp_wait<0>();
        }
        __syncthreads();

        const int st = kt & 1;
        const __half* ks = Ks + st * KST;
        const __half* vs = Vs + st * KST;

        if (k0 <= warp_qmax) {
            float s[8][4];
#pragma unroll
            for (int nf = 0; nf < 8; nf++)
#pragma unroll
                for (int e = 0; e < 4; e++) s[nf][e] = 0.f;

#pragma unroll
            for (int kk = 0; kk < 8; kk++) {
                uint32_t bf[8][2];
#pragma unroll
                for (int j = 0; j < 4; j++) {
                    uint32_t r0, r1, r2, r3;
                    ldsm4(r0, r1, r2, r3,
                          ks + (j * 16 + b_row) * KPITCH + kk * 16 + b_col);
                    bf[2 * j][0] = r0; bf[2 * j][1] = r1;
                    bf[2 * j + 1][0] = r2; bf[2 * j + 1][1] = r3;
                }
#pragma unroll
                for (int nf = 0; nf < 8; nf++) mma_f16(s[nf], qf[kk], bf[nf]);
            }

            float mx0 = -1e30f, mx1 = -1e30f;
#pragma unroll
            for (int nf = 0; nf < 8; nf++)
#pragma unroll
                for (int e = 0; e < 4; e++) {
                    int col = k0 + nf * 8 + la3 * 2 + (e & 1);
                    int qr  = qrow0 + ((e >= 2) ? 8 : 0);
                    float v = s[nf][e] * sc;
                    if (col > qr) v = -1e30f;
                    s[nf][e] = v;
                    if (e < 2) { mx0 = fmaxf(mx0, v); } else { mx1 = fmaxf(mx1, v); }
                }
            mx0 = fmaxf(mx0, __shfl_xor_sync(0xffffffff, mx0, 1));
            mx0 = fmaxf(mx0, __shfl_xor_sync(0xffffffff, mx0, 2));
            mx1 = fmaxf(mx1, __shfl_xor_sync(0xffffffff, mx1, 1));
            mx1 = fmaxf(mx1, __shfl_xor_sync(0xffffffff, mx1, 2));

            float mn0 = fmaxf(m_prev0, mx0);
            float mn1 = fmaxf(m_prev1, mx1);

            float sum0 = 0.f, sum1 = 0.f;
#pragma unroll
            for (int nf = 0; nf < 8; nf++)
#pragma unroll
                for (int e = 0; e < 4; e++) {
                    float p = __expf(s[nf][e] - ((e < 2) ? mn0 : mn1));
                    s[nf][e] = p;
                    if (e < 2) sum0 += p; else sum1 += p;
                }
            sum0 += __shfl_xor_sync(0xffffffff, sum0, 1);
            sum0 += __shfl_xor_sync(0xffffffff, sum0, 2);
            sum1 += __shfl_xor_sync(0xffffffff, sum1, 1);
            sum1 += __shfl_xor_sync(0xffffffff, sum1, 2);

            float corr0 = __expf(m_prev0 - mn0);
            float corr1 = __expf(m_prev1 - mn1);
            l0 = l0 * corr0 + sum0;
            l1 = l1 * corr1 + sum1;
            m_prev0 = mn0; m_prev1 = mn1;

#pragma unroll
            for (int nf = 0; nf < 16; nf++) {
                o[nf][0] *= corr0; o[nf][1] *= corr0;
                o[nf][2] *= corr1; o[nf][3] *= corr1;
            }

            uint32_t ph[4][4];
#pragma unroll
            for (int kk2 = 0; kk2 < 4; kk2++) {
                __half2 h;
                h = __floats2half2_rn(s[2 * kk2][0], s[2 * kk2][1]);         ph[kk2][0] = *(uint32_t*)&h;
                h = __floats2half2_rn(s[2 * kk2][2], s[2 * kk2][3]);         ph[kk2][1] = *(uint32_t*)&h;
                h = __floats2half2_rn(s[2 * kk2 + 1][0], s[2 * kk2 + 1][1]); ph[kk2][2] = *(uint32_t*)&h;
                h = __floats2half2_rn(s[2 * kk2 + 1][2], s[2 * kk2 + 1][3]); ph[kk2][3] = *(uint32_t*)&h;
            }

#pragma unroll
            for (int kk2 = 0; kk2 < 4; kk2++) {
#pragma unroll
                for (int j = 0; j < 8; j++) {
                    uint32_t r0, r1, r2, r3;
                    ldsm4t(r0, r1, r2, r3,
                           vs + (kk2 * 16 + v_row) * KPITCH + j * 16 + v_col);
                    uint32_t bf0[2] = {r0, r1};
                    uint32_t bf1[2] = {r2, r3};
                    mma_f16(o[2 * j], ph[kk2], bf0);
                    mma_f16(o[2 * j + 1], ph[kk2], bf1);
                }
            }
        }
        __syncthreads();
    }

    const int b = bh >> 4, h = bh & 15;
    float inv0 = 1.f / l0, inv1 = 1.f / l1;
#pragma unroll
    for (int nf = 0; nf < 16; nf++)
#pragma unroll
        for (int ep = 0; ep < 2; ep++) {
            int q = qrow0 + ep * 8;
            int v = nf * 8 + la3 * 2;
            float inv = ep ? inv1 : inv0;
            __half2 h2 = __floats2half2_rn(o[nf][2 * ep] * inv, o[nf][2 * ep + 1] * inv);
            *(__half2*)&g_Attn[((size_t)b * S_LEN + q) * DM + h * DK + v] = h2;
        }
}

// ============================================================================
// launch
// ============================================================================
extern "C" void kernel_launch(void* const* d_in, const int* in_sizes, int n_in,
                              void* d_out, int out_size) {
    const float* x  = (const float*)d_in[0];
    const float* WQ = (const float*)d_in[1];
    const float* WK = (const float*)d_in[2];
    const float* WV = (const float*)d_in[3];
    const float* WO = (const float*)d_in[4];
    float* out = (float*)d_out;

    __half *pQ, *pK, *pV, *pA, *pXh, *pWh;
    cudaGetSymbolAddress((void**)&pQ,  g_Q);
    cudaGetSymbolAddress((void**)&pK,  g_K);
    cudaGetSymbolAddress((void**)&pV,  g_V);
    cudaGetSymbolAddress((void**)&pA,  g_Attn);
    cudaGetSymbolAddress((void**)&pXh, g_xh);
    cudaGetSymbolAddress((void**)&pWh, g_Wh);

    const size_t WSZ = (size_t)DM * DM;
    const int flash_smem = 4 * KST * 2;                 // 69632
    cudaFuncSetAttribute(gemm_nt<0>, cudaFuncAttributeMaxDynamicSharedMemorySize, GEMM_SMEM);
    cudaFuncSetAttribute(gemm_nt<1>, cudaFuncAttributeMaxDynamicSharedMemorySize, GEMM_SMEM);
    cudaFuncSetAttribute(flash_attn, cudaFuncAttributeMaxDynamicSharedMemorySize, flash_smem);

    // one fused conversion launch: 8 equal slices (4x quarters of x, 4 weights)
    cvt_all<<<dim3(96, 8), 256>>>(x, WQ, WK, WV, WO, pXh, pWh);

    // fused QKV projection: gridDim.z selects weight/output
    dim3 qkv_grid(16, 64, 3);   // N/128, M/128, {Q,K,V}
    gemm_nt<1><<<qkv_grid, 256, GEMM_SMEM>>>(pXh, pWh, pQ, pK, pV);

    dim3 fgrid(16, 64);
    flash_attn<<<fgrid, 256, flash_smem>>>();

    dim3 o_grid(16, 64, 1);
    gemm_nt<0><<<o_grid, 256, GEMM_SMEM>>>(pA, pWh + 3 * WSZ, out, nullptr, nullptr);
}